// round 13
// baseline (speedup 1.0000x reference)
#include <cuda_runtime.h>
#include <cuda_fp16.h>
#include <math_constants.h>

// Problem constants
#define Bdim   4
#define Tdim   2048
#define Hdim   512
#define NHEADS 8
#define Ddim   64
#define Mdim   (Bdim * Tdim)          // 8192
#define QKVN   (3 * Hdim)             // 1536

// fp16 scratch (allocation-free rule: __device__ globals)
__device__ __half g_xh[(size_t)Mdim * Hdim];
__device__ __half g_wqkvh[(size_t)Hdim * QKVN];   // [K][N] row-major
__device__ __half g_wprojh[(size_t)Hdim * Hdim];  // [K][N] row-major
__device__ __half g_qkvh[(size_t)Mdim * QKVN];
__device__ __half g_attnh[(size_t)Mdim * Hdim];

// ---------------------------------------------------------------------------
// PTX helpers
// ---------------------------------------------------------------------------
__device__ __forceinline__ unsigned smem_u32(const void* p) {
    return (unsigned)__cvta_generic_to_shared(p);
}
__device__ __forceinline__ void cp16(unsigned dst, const void* src) {
    asm volatile("cp.async.cg.shared.global [%0], [%1], 16;"
                 :: "r"(dst), "l"(src));
}
#define CP_COMMIT asm volatile("cp.async.commit_group;")
#define CP_WAIT(n) asm volatile("cp.async.wait_group %0;" :: "n"(n))

__device__ __forceinline__ void ldsm4(unsigned* d, unsigned a) {
    asm volatile("ldmatrix.sync.aligned.m8n8.x4.shared.b16 {%0,%1,%2,%3}, [%4];"
                 : "=r"(d[0]), "=r"(d[1]), "=r"(d[2]), "=r"(d[3]) : "r"(a));
}
__device__ __forceinline__ void ldsm4t(unsigned* d, unsigned a) {
    asm volatile("ldmatrix.sync.aligned.m8n8.x4.trans.shared.b16 {%0,%1,%2,%3}, [%4];"
                 : "=r"(d[0]), "=r"(d[1]), "=r"(d[2]), "=r"(d[3]) : "r"(a));
}
// f32-accumulate mma
__device__ __forceinline__ void mma16(float* c, const unsigned* a, const unsigned* b) {
    asm volatile(
        "mma.sync.aligned.m16n8k16.row.col.f32.f16.f16.f32 "
        "{%0,%1,%2,%3},{%4,%5,%6,%7},{%8,%9},{%0,%1,%2,%3};"
        : "+f"(c[0]), "+f"(c[1]), "+f"(c[2]), "+f"(c[3])
        : "r"(a[0]), "r"(a[1]), "r"(a[2]), "r"(a[3]), "r"(b[0]), "r"(b[1]));
}
// f16-accumulate mma (2-reg C fragment)
__device__ __forceinline__ void mma16h(unsigned* c, const unsigned* a, const unsigned* b) {
    asm volatile(
        "mma.sync.aligned.m16n8k16.row.col.f16.f16.f16.f16 "
        "{%0,%1},{%2,%3,%4,%5},{%6,%7},{%0,%1};"
        : "+r"(c[0]), "+r"(c[1])
        : "r"(a[0]), "r"(a[1]), "r"(a[2]), "r"(a[3]), "r"(b[0]), "r"(b[1]));
}
__device__ __forceinline__ unsigned ex2h2(unsigned u) {
    unsigned r;
    asm("ex2.approx.f16x2 %0, %1;" : "=r"(r) : "r"(u));
    return r;
}
__device__ __forceinline__ unsigned hfma2u(unsigned a, unsigned b, unsigned c) {
    unsigned d;
    asm("fma.rn.f16x2 %0,%1,%2,%3;" : "=r"(d) : "r"(a), "r"(b), "r"(c));
    return d;
}
__device__ __forceinline__ unsigned packh2c(float a, float b) {
    __half2 h = __floats2half2_rn(a, b);
    return *reinterpret_cast<unsigned*>(&h);
}

// ---------------------------------------------------------------------------
// fp32 -> fp16 conversion, all three tensors in ONE launch (range dispatch)
// ---------------------------------------------------------------------------
__global__ __launch_bounds__(256) void f2h_all(
    const float* __restrict__ x,     __half* __restrict__ xh,
    const float* __restrict__ wqkv,  __half* __restrict__ wqkvh,
    const float* __restrict__ wproj, __half* __restrict__ wprojh)
{
    const float* in; __half* out; int base;
    const int bid = blockIdx.x;
    if (bid < 4096)      { in = x;     out = xh;     base = bid; }
    else if (bid < 4864) { in = wqkv;  out = wqkvh;  base = bid - 4096; }
    else                 { in = wproj; out = wprojh; base = bid - 4864; }
    const int i = (base * 256 + threadIdx.x) * 4;
    float4 v = *(const float4*)(in + i);
    *(__half2*)(out + i)     = __floats2half2_rn(v.x, v.y);
    *(__half2*)(out + i + 2) = __floats2half2_rn(v.z, v.w);
}

// ---------------------------------------------------------------------------
// fp16 GEMM + fp32 bias. BM=128 BN=128 BK=64, 8 warps (2m x 4n), warp tile
// 64x32. 3-stage cp.async pipeline, ONE barrier per chunk. 96KB smem,
// 2 CTAs/SM. Stage s at s*32768: A (16KB) | W (16KB).
// ---------------------------------------------------------------------------
template<bool OUTH>
__global__ __launch_bounds__(256, 2) void gemm_h(
    const __half* __restrict__ A, const __half* __restrict__ W,
    const float* __restrict__ bias, void* __restrict__ Cout,
    int M, int N, int K)
{
    extern __shared__ char smc[];
    const unsigned smb = smem_u32(smc);
    const int tid = threadIdx.x, lane = tid & 31, warp = tid >> 5;
    const int wm = warp & 1;
    const int wn = warp >> 1;
    const int m0 = blockIdx.y * 128, n0 = blockIdx.x * 128;
    const int NKT = K / 64;

    auto loadAW = [&](int kt, int s) {
        const unsigned base = smb + s * 32768;
        #pragma unroll
        for (int l = 0; l < 4; l++) {
            int id = tid + l * 256, r = id >> 3, c = id & 7;
            cp16(base + r * 128 + ((c ^ (r & 7)) * 16),
                 A + (size_t)(m0 + r) * K + kt + c * 8);
        }
        #pragma unroll
        for (int l = 0; l < 4; l++) {
            int id = tid + l * 256, r = id >> 4, c = id & 15;
            cp16(base + 16384 + r * 256 + ((c ^ (r & 7)) * 16),
                 W + (size_t)(kt + r) * N + n0 + c * 8);
        }
    };

    loadAW(0, 0);  CP_COMMIT;
    loadAW(64, 1); CP_COMMIT;

    float c[4][4][4] = {};

    for (int i = 0; i < NKT; i++) {
        CP_WAIT(1);
        __syncthreads();
        if (i + 2 < NKT) loadAW((i + 2) * 64, (i + 2) % 3);
        CP_COMMIT;
        const unsigned ab = smb + (i % 3) * 32768;
        const unsigned wb = ab + 16384;

        #pragma unroll
        for (int kk = 0; kk < 4; kk++) {
            unsigned af[4][4], bf[2][4];
            #pragma unroll
            for (int mt = 0; mt < 4; mt++) {
                int row = wm * 64 + mt * 16 + (lane & 7) + (lane & 8);
                int ch  = 2 * kk + (lane >> 4);
                ldsm4(af[mt], ab + row * 128 + ((ch ^ (row & 7)) * 16));
            }
            #pragma unroll
            for (int p = 0; p < 2; p++) {
                int row = kk * 16 + (lane & 7) + (lane & 8);
                int ch  = wn * 4 + 2 * p + (lane >> 4);
                ldsm4t(bf[p], wb + row * 256 + ((ch ^ (row & 7)) * 16));
            }
            #pragma unroll
            for (int mt = 0; mt < 4; mt++)
                #pragma unroll
                for (int p = 0; p < 2; p++) {
                    mma16(c[mt][2 * p],     af[mt], bf[p]);
                    mma16(c[mt][2 * p + 1], af[mt], bf[p] + 2);
                }
        }
    }

    #pragma unroll
    for (int mt = 0; mt < 4; mt++) {
        int r = m0 + wm * 64 + mt * 16 + (lane >> 2);
        #pragma unroll
        for (int nt = 0; nt < 4; nt++) {
            int cc = n0 + wn * 32 + nt * 8 + (lane & 3) * 2;
            float2 b2 = *(const float2*)(bias + cc);
            float v0 = c[mt][nt][0] + b2.x, v1 = c[mt][nt][1] + b2.y;
            float v2 = c[mt][nt][2] + b2.x, v3 = c[mt][nt][3] + b2.y;
            if (OUTH) {
                __half* C = (__half*)Cout;
                *(__half2*)(C + (size_t)r * N + cc)       = __floats2half2_rn(v0, v1);
                *(__half2*)(C + (size_t)(r + 8) * N + cc) = __floats2half2_rn(v2, v3);
            } else {
                float* C = (float*)Cout;
                *(float2*)(C + (size_t)r * N + cc)       = make_float2(v0, v1);
                *(float2*)(C + (size_t)(r + 8) * N + cc) = make_float2(v2, v3);
            }
        }
    }
}

// ---------------------------------------------------------------------------
// fp16 flash attention v13 — fused per-strip QK->exp->PV:
//  For each 16-KV-row strip: QK mma (fp16 acc) -> static-max exp (f16x2)
//  -> PV mma immediately. No S-tile buffer (saves 28 regs), MUFU overlaps
//  HMMA, ~75 regs -> 3 CTAs/SM (85-reg cap) with 64KB smem.
//  4-stage KV pipeline (16KB/stage: K 8KB | V 8KB), Q staged through
//  stage 0 then in regs; ONE __syncthreads per iter.
// Smem 64KB, 3 CTAs/SM (192KB/SM). Grid (T/128, B*HEADS) = (16,32) = 512
// over 444 slots = 1.15 waves.
// ---------------------------------------------------------------------------
__global__ __launch_bounds__(256, 3) void flash_h(
    const __half* __restrict__ qkv, __half* __restrict__ attn)
{
    extern __shared__ char smc[];
    const unsigned smb = smem_u32(smc);
    const int tid = threadIdx.x, lane = tid & 31, w = tid >> 5;
    const int bh = blockIdx.y, b = bh >> 3, h = bh & 7;
    const int q0 = blockIdx.x * 128;
    const unsigned FULL = 0xffffffffu;
    const float C2 = 0.125f * 1.44269504089f;   // scale * log2(e)
    const float M0 = 6.0f;                      // static max bound
    const unsigned C2h = packh2c(C2, C2);
    const unsigned cMh = packh2c(-M0 * 1.44269504089f, -M0 * 1.44269504089f);
    const int NT = Tdim / 64;                   // 32

    // Ones-column B fragment: 1.0 in every k of col 0 (lane>>2 == 0).
    const unsigned ONE1 = ((lane >> 2) == 0) ? 0x3C003C00u : 0u;
    const unsigned onesb[2] = {ONE1, ONE1};

    // --- Prologue: Q (128 rows x 128B = 16KB) through stage 0
    #pragma unroll
    for (int l = 0; l < 4; l++) {
        int id = tid + l * 256, r = id >> 3, c = id & 7;
        cp16(smb + r * 128 + ((c ^ (r & 7)) * 16),
             qkv + (size_t)(b * Tdim + q0 + r) * QKVN + h * Ddim + c * 8);
    }
    CP_COMMIT;
    CP_WAIT(0);
    __syncthreads();

    unsigned qa[4][4];
    #pragma unroll
    for (int kk = 0; kk < 4; kk++) {
        int row = w * 16 + (lane & 7) + (lane & 8);
        int ch  = 2 * kk + (lane >> 4);
        ldsm4(qa[kk], smb + row * 128 + ((ch ^ (row & 7)) * 16));
    }
    __syncthreads();     // all warps done reading Q before stage 0 is reused

    // KV tile: 64 rows. Stage s at s*16384: K at +0, V at +8192.
    auto loadKV = [&](int t64, int s) {
        #pragma unroll
        for (int l = 0; l < 4; l++) {
            int id = tid + l * 256;             // 1024 chunks: 512 K + 512 V
            int hs = id >> 9, rid = id & 511;
            int r = rid >> 3, c = rid & 7;
            cp16(smb + s * 16384 + hs * 8192 + r * 128 + ((c ^ (r & 7)) * 16),
                 qkv + (size_t)(b * Tdim + t64 * 64 + r) * QKVN
                     + (1 + hs) * Hdim + h * Ddim + c * 8);
        }
    };
    loadKV(0, 0); CP_COMMIT;
    loadKV(1, 1); CP_COMMIT;
    loadKV(2, 2); CP_COMMIT;

    float o[8][4] = {};
    float ol[4] = {};                    // ones-column accumulator (l sums)

    for (int t = 0; t < NT; t++) {
        CP_WAIT(2);          // stage t complete
        __syncthreads();     // stage (t+3)&3 free (last read at t-1)
        if (t + 3 < NT) loadKV(t + 3, (t + 3) & 3);
        CP_COMMIT;           // unconditional: keeps group accounting exact
        const unsigned kvb = smb + (t & 3) * 16384;

        // Fused per-strip: 4 strips of 16 KV rows
        #pragma unroll
        for (int p = 0; p < 4; p++) {
            // S strip = Q @ K_strip^T (fp16 acc, 2 n-tiles x 2 regs)
            unsigned sf[4] = {0u, 0u, 0u, 0u};
            #pragma unroll
            for (int kk = 0; kk < 4; kk++) {
                unsigned kb[4];
                int row = p * 16 + (lane & 7) + ((lane >> 4) << 3);
                int ch  = 2 * kk + ((lane >> 3) & 1);
                ldsm4(kb, kvb + row * 128 + ((ch ^ (row & 7)) * 16));
                mma16h(sf,     qa[kk], kb);
                mma16h(sf + 2, qa[kk], kb + 2);
            }
            // Static-max exp in place -> PV A-fragment
            unsigned pa[4];
            pa[0] = ex2h2(hfma2u(sf[0], C2h, cMh));
            pa[1] = ex2h2(hfma2u(sf[1], C2h, cMh));
            pa[2] = ex2h2(hfma2u(sf[2], C2h, cMh));
            pa[3] = ex2h2(hfma2u(sf[3], C2h, cMh));
            // O += P_strip @ V_strip; l += P_strip @ ones
            #pragma unroll
            for (int d = 0; d < 4; d++) {
                unsigned vb[4];
                int row = p * 16 + (lane & 7) + (lane & 8);
                int ch  = 2 * d + (lane >> 4);
                ldsm4t(vb, kvb + 8192 + row * 128 + ((ch ^ (row & 7)) * 16));
                mma16(o[2 * d],     pa, vb);
                mma16(o[2 * d + 1], pa, vb + 2);
            }
            mma16(ol, pa, onesb);
        }
    }

    // l lives in column 0 of the ones tile: quad leader's regs 0 / 2
    const float lA = __shfl_sync(FULL, ol[0], lane & ~3);
    const float lB = __shfl_sync(FULL, ol[2], lane & ~3);
    const float iA = 1.f / lA, iB = 1.f / lB;
    const int rA = q0 + w * 16 + (lane >> 2);
    #pragma unroll
    for (int p = 0; p < 8; p++) {
        int col = h * Ddim + p * 8 + (lane & 3) * 2;
        *(__half2*)(attn + (size_t)(b * Tdim + rA) * Hdim + col) =
            __floats2half2_rn(o[p][0] * iA, o[p][1] * iA);
        *(__half2*)(attn + (size_t)(b * Tdim + rA + 8) * Hdim + col) =
            __floats2half2_rn(o[p][2] * iB, o[p][3] * iB);
    }
}

// ---------------------------------------------------------------------------
// Launch
// ---------------------------------------------------------------------------
extern "C" void kernel_launch(void* const* d_in, const int* in_sizes, int n_in,
                              void* d_out, int out_size)
{
    const float* x      = (const float*)d_in[0];
    const float* w_qkv  = (const float*)d_in[1];
    const float* b_qkv  = (const float*)d_in[2];
    const float* w_proj = (const float*)d_in[3];
    const float* b_proj = (const float*)d_in[4];
    float* out = (float*)d_out;

    __half *xh, *wqkvh, *wprojh, *qkvh, *attnh;
    cudaGetSymbolAddress((void**)&xh, g_xh);
    cudaGetSymbolAddress((void**)&wqkvh, g_wqkvh);
    cudaGetSymbolAddress((void**)&wprojh, g_wprojh);
    cudaGetSymbolAddress((void**)&qkvh, g_qkvh);
    cudaGetSymbolAddress((void**)&attnh, g_attnh);

    // 0) all fp32 -> fp16 conversions in one launch
    f2h_all<<<5120, 256>>>(x, xh, w_qkv, wqkvh, w_proj, wprojh);

    // 1) QKV projection (fp16 out), 96KB smem
    cudaFuncSetAttribute(gemm_h<true>,
                         cudaFuncAttributeMaxDynamicSharedMemorySize, 98304);
    gemm_h<true><<<dim3(QKVN / 128, Mdim / 128), 256, 98304>>>(
        xh, wqkvh, b_qkv, qkvh, Mdim, QKVN, Hdim);

    // 2) Flash attention (fp16 out), 64KB smem, 3 CTAs/SM
    cudaFuncSetAttribute(flash_h,
                         cudaFuncAttributeMaxDynamicSharedMemorySize, 65536);
    flash_h<<<dim3(Tdim / 128, Bdim * NHEADS), 256, 65536>>>(qkvh, attnh);

    // 3) Output projection (fp32 out), 96KB smem
    cudaFuncSetAttribute(gemm_h<false>,
                         cudaFuncAttributeMaxDynamicSharedMemorySize, 98304);
    gemm_h<false><<<dim3(Hdim / 128, Mdim / 128), 256, 98304>>>(
        attnh, wprojh, b_proj, out, Mdim, Hdim, Hdim);
}

// round 14
// speedup vs baseline: 1.0365x; 1.0365x over previous
#include <cuda_runtime.h>
#include <cuda_fp16.h>
#include <math_constants.h>

// Problem constants
#define Bdim   4
#define Tdim   2048
#define Hdim   512
#define NHEADS 8
#define Ddim   64
#define Mdim   (Bdim * Tdim)          // 8192
#define QKVN   (3 * Hdim)             // 1536

// fp16 scratch (allocation-free rule: __device__ globals)
__device__ __half g_xh[(size_t)Mdim * Hdim];
__device__ __half g_wqkvh[(size_t)Hdim * QKVN];   // [K][N] row-major
__device__ __half g_wprojh[(size_t)Hdim * Hdim];  // [K][N] row-major
__device__ __half g_qkvh[(size_t)Mdim * QKVN];
__device__ __half g_attnh[(size_t)Mdim * Hdim];

// ---------------------------------------------------------------------------
// PTX helpers
// ---------------------------------------------------------------------------
__device__ __forceinline__ unsigned smem_u32(const void* p) {
    return (unsigned)__cvta_generic_to_shared(p);
}
__device__ __forceinline__ void cp16(unsigned dst, const void* src) {
    asm volatile("cp.async.cg.shared.global [%0], [%1], 16;"
                 :: "r"(dst), "l"(src));
}
#define CP_COMMIT asm volatile("cp.async.commit_group;")
#define CP_WAIT(n) asm volatile("cp.async.wait_group %0;" :: "n"(n))

__device__ __forceinline__ void ldsm4(unsigned* d, unsigned a) {
    asm volatile("ldmatrix.sync.aligned.m8n8.x4.shared.b16 {%0,%1,%2,%3}, [%4];"
                 : "=r"(d[0]), "=r"(d[1]), "=r"(d[2]), "=r"(d[3]) : "r"(a));
}
__device__ __forceinline__ void ldsm4t(unsigned* d, unsigned a) {
    asm volatile("ldmatrix.sync.aligned.m8n8.x4.trans.shared.b16 {%0,%1,%2,%3}, [%4];"
                 : "=r"(d[0]), "=r"(d[1]), "=r"(d[2]), "=r"(d[3]) : "r"(a));
}
// f32-accumulate mma
__device__ __forceinline__ void mma16(float* c, const unsigned* a, const unsigned* b) {
    asm volatile(
        "mma.sync.aligned.m16n8k16.row.col.f32.f16.f16.f32 "
        "{%0,%1,%2,%3},{%4,%5,%6,%7},{%8,%9},{%0,%1,%2,%3};"
        : "+f"(c[0]), "+f"(c[1]), "+f"(c[2]), "+f"(c[3])
        : "r"(a[0]), "r"(a[1]), "r"(a[2]), "r"(a[3]), "r"(b[0]), "r"(b[1]));
}
// f16-accumulate mma (2-reg C fragment)
__device__ __forceinline__ void mma16h(unsigned* c, const unsigned* a, const unsigned* b) {
    asm volatile(
        "mma.sync.aligned.m16n8k16.row.col.f16.f16.f16.f16 "
        "{%0,%1},{%2,%3,%4,%5},{%6,%7},{%0,%1};"
        : "+r"(c[0]), "+r"(c[1])
        : "r"(a[0]), "r"(a[1]), "r"(a[2]), "r"(a[3]), "r"(b[0]), "r"(b[1]));
}
__device__ __forceinline__ unsigned ex2h2(unsigned u) {
    unsigned r;
    asm("ex2.approx.f16x2 %0, %1;" : "=r"(r) : "r"(u));
    return r;
}
__device__ __forceinline__ unsigned hfma2u(unsigned a, unsigned b, unsigned c) {
    unsigned d;
    asm("fma.rn.f16x2 %0,%1,%2,%3;" : "=r"(d) : "r"(a), "r"(b), "r"(c));
    return d;
}
__device__ __forceinline__ unsigned packh2c(float a, float b) {
    __half2 h = __floats2half2_rn(a, b);
    return *reinterpret_cast<unsigned*>(&h);
}

// ---------------------------------------------------------------------------
// fp32 -> fp16 conversion, all three tensors in ONE launch (range dispatch)
// ---------------------------------------------------------------------------
__global__ __launch_bounds__(256) void f2h_all(
    const float* __restrict__ x,     __half* __restrict__ xh,
    const float* __restrict__ wqkv,  __half* __restrict__ wqkvh,
    const float* __restrict__ wproj, __half* __restrict__ wprojh)
{
    const float* in; __half* out; int base;
    const int bid = blockIdx.x;
    if (bid < 4096)      { in = x;     out = xh;     base = bid; }
    else if (bid < 4864) { in = wqkv;  out = wqkvh;  base = bid - 4096; }
    else                 { in = wproj; out = wprojh; base = bid - 4864; }
    const int i = (base * 256 + threadIdx.x) * 4;
    float4 v = *(const float4*)(in + i);
    *(__half2*)(out + i)     = __floats2half2_rn(v.x, v.y);
    *(__half2*)(out + i + 2) = __floats2half2_rn(v.z, v.w);
}

// ---------------------------------------------------------------------------
// fp16 GEMM + fp32 bias (proven). BM=128 BN=128 BK=64, 8 warps (2m x 4n),
// warp tile 64x32. 3-stage cp.async pipeline, ONE barrier per chunk.
// 96KB smem, 2 CTAs/SM.
// ---------------------------------------------------------------------------
template<bool OUTH>
__global__ __launch_bounds__(256, 2) void gemm_h(
    const __half* __restrict__ A, const __half* __restrict__ W,
    const float* __restrict__ bias, void* __restrict__ Cout,
    int M, int N, int K)
{
    extern __shared__ char smc[];
    const unsigned smb = smem_u32(smc);
    const int tid = threadIdx.x, lane = tid & 31, warp = tid >> 5;
    const int wm = warp & 1;
    const int wn = warp >> 1;
    const int m0 = blockIdx.y * 128, n0 = blockIdx.x * 128;
    const int NKT = K / 64;

    auto loadAW = [&](int kt, int s) {
        const unsigned base = smb + s * 32768;
        #pragma unroll
        for (int l = 0; l < 4; l++) {
            int id = tid + l * 256, r = id >> 3, c = id & 7;
            cp16(base + r * 128 + ((c ^ (r & 7)) * 16),
                 A + (size_t)(m0 + r) * K + kt + c * 8);
        }
        #pragma unroll
        for (int l = 0; l < 4; l++) {
            int id = tid + l * 256, r = id >> 4, c = id & 15;
            cp16(base + 16384 + r * 256 + ((c ^ (r & 7)) * 16),
                 W + (size_t)(kt + r) * N + n0 + c * 8);
        }
    };

    loadAW(0, 0);  CP_COMMIT;
    loadAW(64, 1); CP_COMMIT;

    float c[4][4][4] = {};

    for (int i = 0; i < NKT; i++) {
        CP_WAIT(1);
        __syncthreads();
        if (i + 2 < NKT) loadAW((i + 2) * 64, (i + 2) % 3);
        CP_COMMIT;
        const unsigned ab = smb + (i % 3) * 32768;
        const unsigned wb = ab + 16384;

        #pragma unroll
        for (int kk = 0; kk < 4; kk++) {
            unsigned af[4][4], bf[2][4];
            #pragma unroll
            for (int mt = 0; mt < 4; mt++) {
                int row = wm * 64 + mt * 16 + (lane & 7) + (lane & 8);
                int ch  = 2 * kk + (lane >> 4);
                ldsm4(af[mt], ab + row * 128 + ((ch ^ (row & 7)) * 16));
            }
            #pragma unroll
            for (int p = 0; p < 2; p++) {
                int row = kk * 16 + (lane & 7) + (lane & 8);
                int ch  = wn * 4 + 2 * p + (lane >> 4);
                ldsm4t(bf[p], wb + row * 256 + ((ch ^ (row & 7)) * 16));
            }
            #pragma unroll
            for (int mt = 0; mt < 4; mt++)
                #pragma unroll
                for (int p = 0; p < 2; p++) {
                    mma16(c[mt][2 * p],     af[mt], bf[p]);
                    mma16(c[mt][2 * p + 1], af[mt], bf[p] + 2);
                }
        }
    }

    #pragma unroll
    for (int mt = 0; mt < 4; mt++) {
        int r = m0 + wm * 64 + mt * 16 + (lane >> 2);
        #pragma unroll
        for (int nt = 0; nt < 4; nt++) {
            int cc = n0 + wn * 32 + nt * 8 + (lane & 3) * 2;
            float2 b2 = *(const float2*)(bias + cc);
            float v0 = c[mt][nt][0] + b2.x, v1 = c[mt][nt][1] + b2.y;
            float v2 = c[mt][nt][2] + b2.x, v3 = c[mt][nt][3] + b2.y;
            if (OUTH) {
                __half* C = (__half*)Cout;
                *(__half2*)(C + (size_t)r * N + cc)       = __floats2half2_rn(v0, v1);
                *(__half2*)(C + (size_t)(r + 8) * N + cc) = __floats2half2_rn(v2, v3);
            } else {
                float* C = (float*)Cout;
                *(float2*)(C + (size_t)r * N + cc)       = make_float2(v0, v1);
                *(float2*)(C + (size_t)(r + 8) * N + cc) = make_float2(v2, v3);
            }
        }
    }
}

// ---------------------------------------------------------------------------
// fp16 flash attention v14 — 2 q-tiles/warp + static-max fused strips:
//  CTA covers 256 q rows; warp w owns rows w*16.. and 128+w*16... Each
//  kb/vb fragment load feeds BOTH q-tiles -> per-q-row crossbar traffic
//  halved (the R12 binder). The two independent q-tile chains provide the
//  ILP that R13's single-tile fusion lacked. Static-max softmax: one
//  fma.f16x2 + one ex2.f16x2 per pair; exact normalization via tensor-core
//  ones-column l (f32).
//  4-stage KV pipeline (16KB/stage: K 8KB | V 8KB) = 64KB -> 2 CTAs/SM.
//  Q (32KB) staged through stages 0-1 before the KV stream starts.
// Grid (T/256, B*HEADS) = (8,32) = 256 CTAs over 296 slots = 0.86 waves.
// ---------------------------------------------------------------------------
__global__ __launch_bounds__(256, 2) void flash_h(
    const __half* __restrict__ qkv, __half* __restrict__ attn)
{
    extern __shared__ char smc[];
    const unsigned smb = smem_u32(smc);
    const int tid = threadIdx.x, lane = tid & 31, w = tid >> 5;
    const int bh = blockIdx.y, b = bh >> 3, h = bh & 7;
    const int q0 = blockIdx.x * 256;
    const unsigned FULL = 0xffffffffu;
    const float C2 = 0.125f * 1.44269504089f;   // scale * log2(e)
    const float M0 = 6.0f;                      // static max bound
    const unsigned C2h = packh2c(C2, C2);
    const unsigned cMh = packh2c(-M0 * 1.44269504089f, -M0 * 1.44269504089f);
    const int NT = Tdim / 64;                   // 32

    // Ones-column B fragment: 1.0 in every k of col 0 (lane>>2 == 0).
    const unsigned ONE1 = ((lane >> 2) == 0) ? 0x3C003C00u : 0u;
    const unsigned onesb[2] = {ONE1, ONE1};

    // --- Prologue: Q (256 rows x 128B = 32KB) through stages 0-1
    #pragma unroll
    for (int l = 0; l < 8; l++) {
        int id = tid + l * 256, r = id >> 3, c = id & 7;
        cp16(smb + r * 128 + ((c ^ (r & 7)) * 16),
             qkv + (size_t)(b * Tdim + q0 + r) * QKVN + h * Ddim + c * 8);
    }
    CP_COMMIT;
    CP_WAIT(0);
    __syncthreads();

    unsigned qa[2][4][4];
    #pragma unroll
    for (int qt = 0; qt < 2; qt++)
        #pragma unroll
        for (int kk = 0; kk < 4; kk++) {
            int row = qt * 128 + w * 16 + (lane & 7) + (lane & 8);
            int ch  = 2 * kk + (lane >> 4);
            ldsm4(qa[qt][kk], smb + row * 128 + ((ch ^ (row & 7)) * 16));
        }
    __syncthreads();     // all warps done reading Q before stages are reused

    // KV tile: 64 rows. Stage s at s*16384: K at +0, V at +8192.
    auto loadKV = [&](int t64, int s) {
        #pragma unroll
        for (int l = 0; l < 4; l++) {
            int id = tid + l * 256;             // 1024 chunks: 512 K + 512 V
            int hs = id >> 9, rid = id & 511;
            int r = rid >> 3, c = rid & 7;
            cp16(smb + s * 16384 + hs * 8192 + r * 128 + ((c ^ (r & 7)) * 16),
                 qkv + (size_t)(b * Tdim + t64 * 64 + r) * QKVN
                     + (1 + hs) * Hdim + h * Ddim + c * 8);
        }
    };
    loadKV(0, 0); CP_COMMIT;
    loadKV(1, 1); CP_COMMIT;
    loadKV(2, 2); CP_COMMIT;

    float o[2][8][4] = {};
    float ol[2][4] = {};                 // ones-column accumulators (l sums)

    for (int t = 0; t < NT; t++) {
        CP_WAIT(2);          // stage t complete
        __syncthreads();     // stage (t+3)&3 free (last read at t-1)
        if (t + 3 < NT) loadKV(t + 3, (t + 3) & 3);
        CP_COMMIT;           // unconditional: keeps group accounting exact
        const unsigned kvb = smb + (t & 3) * 16384;

        // Fused strips: 4 strips of 16 KV rows; kb/vb shared by both q-tiles
        #pragma unroll
        for (int p = 0; p < 4; p++) {
            // S strips = Q @ K_strip^T (fp16 acc)
            unsigned sf[2][4];
            sf[0][0] = sf[0][1] = sf[0][2] = sf[0][3] = 0u;
            sf[1][0] = sf[1][1] = sf[1][2] = sf[1][3] = 0u;
            #pragma unroll
            for (int kk = 0; kk < 4; kk++) {
                unsigned kb[4];
                int row = p * 16 + (lane & 7) + ((lane >> 4) << 3);
                int ch  = 2 * kk + ((lane >> 3) & 1);
                ldsm4(kb, kvb + row * 128 + ((ch ^ (row & 7)) * 16));
                #pragma unroll
                for (int qt = 0; qt < 2; qt++) {
                    mma16h(sf[qt],     qa[qt][kk], kb);
                    mma16h(sf[qt] + 2, qa[qt][kk], kb + 2);
                }
            }
            // Static-max exp in place -> PV A-fragments
            #pragma unroll
            for (int qt = 0; qt < 2; qt++) {
                sf[qt][0] = ex2h2(hfma2u(sf[qt][0], C2h, cMh));
                sf[qt][1] = ex2h2(hfma2u(sf[qt][1], C2h, cMh));
                sf[qt][2] = ex2h2(hfma2u(sf[qt][2], C2h, cMh));
                sf[qt][3] = ex2h2(hfma2u(sf[qt][3], C2h, cMh));
            }
            // O += P_strip @ V_strip (vb shared); l += P_strip @ ones
            #pragma unroll
            for (int d = 0; d < 4; d++) {
                unsigned vb[4];
                int row = p * 16 + (lane & 7) + (lane & 8);
                int ch  = 2 * d + (lane >> 4);
                ldsm4t(vb, kvb + 8192 + row * 128 + ((ch ^ (row & 7)) * 16));
                #pragma unroll
                for (int qt = 0; qt < 2; qt++) {
                    mma16(o[qt][2 * d],     sf[qt], vb);
                    mma16(o[qt][2 * d + 1], sf[qt], vb + 2);
                }
            }
            mma16(ol[0], sf[0], onesb);
            mma16(ol[1], sf[1], onesb);
        }
    }

    // l lives in column 0 of the ones tile: quad leader's regs 0 / 2
    #pragma unroll
    for (int qt = 0; qt < 2; qt++) {
        const float lA = __shfl_sync(FULL, ol[qt][0], lane & ~3);
        const float lB = __shfl_sync(FULL, ol[qt][2], lane & ~3);
        const float iA = 1.f / lA, iB = 1.f / lB;
        const int rA = q0 + qt * 128 + w * 16 + (lane >> 2);
        #pragma unroll
        for (int p = 0; p < 8; p++) {
            int col = h * Ddim + p * 8 + (lane & 3) * 2;
            *(__half2*)(attn + (size_t)(b * Tdim + rA) * Hdim + col) =
                __floats2half2_rn(o[qt][p][0] * iA, o[qt][p][1] * iA);
            *(__half2*)(attn + (size_t)(b * Tdim + rA + 8) * Hdim + col) =
                __floats2half2_rn(o[qt][p][2] * iB, o[qt][p][3] * iB);
        }
    }
}

// ---------------------------------------------------------------------------
// Launch
// ---------------------------------------------------------------------------
extern "C" void kernel_launch(void* const* d_in, const int* in_sizes, int n_in,
                              void* d_out, int out_size)
{
    const float* x      = (const float*)d_in[0];
    const float* w_qkv  = (const float*)d_in[1];
    const float* b_qkv  = (const float*)d_in[2];
    const float* w_proj = (const float*)d_in[3];
    const float* b_proj = (const float*)d_in[4];
    float* out = (float*)d_out;

    __half *xh, *wqkvh, *wprojh, *qkvh, *attnh;
    cudaGetSymbolAddress((void**)&xh, g_xh);
    cudaGetSymbolAddress((void**)&wqkvh, g_wqkvh);
    cudaGetSymbolAddress((void**)&wprojh, g_wprojh);
    cudaGetSymbolAddress((void**)&qkvh, g_qkvh);
    cudaGetSymbolAddress((void**)&attnh, g_attnh);

    // 0) all fp32 -> fp16 conversions in one launch
    f2h_all<<<5120, 256>>>(x, xh, w_qkv, wqkvh, w_proj, wprojh);

    // 1) QKV projection (fp16 out), 96KB smem
    cudaFuncSetAttribute(gemm_h<true>,
                         cudaFuncAttributeMaxDynamicSharedMemorySize, 98304);
    gemm_h<true><<<dim3(QKVN / 128, Mdim / 128), 256, 98304>>>(
        xh, wqkvh, b_qkv, qkvh, Mdim, QKVN, Hdim);

    // 2) Flash attention (fp16 out), 64KB smem, 2 CTAs/SM, single wave
    cudaFuncSetAttribute(flash_h,
                         cudaFuncAttributeMaxDynamicSharedMemorySize, 65536);
    flash_h<<<dim3(Tdim / 256, Bdim * NHEADS), 256, 65536>>>(qkvh, attnh);

    // 3) Output projection (fp32 out), 96KB smem
    cudaFuncSetAttribute(gemm_h<false>,
                         cudaFuncAttributeMaxDynamicSharedMemorySize, 98304);
    gemm_h<false><<<dim3(Hdim / 128, Mdim / 128), 256, 98304>>>(
        attnh, wprojh, b_proj, out, Mdim, Hdim, Hdim);
}